// round 2
// baseline (speedup 1.0000x reference)
#include <cuda_runtime.h>

// Inputs (metadata order):
//  0: link_pos_seq   [1024,32,8,3]    f32
//  1: link_rot_seq   [1024,32,8,3,3]  f32
//  2: sphere_centers [8,8,3]          f32
//  3: sphere_radii   [8,8]            f32
//  4: sdf_grid       [256,256,256]    f32
//  5: weight         scalar           f32
// Output: [1024,32] f32

#define GRID_N 256
#define N_LINKS 8
#define N_SPH 8
#define TB 256

__global__ __launch_bounds__(TB, 6)
void voxel_collision_kernel(const float* __restrict__ pos,
                            const float* __restrict__ rot,
                            const float* __restrict__ cen,
                            const float* __restrict__ rad,
                            const float* __restrict__ sdf,
                            const float* __restrict__ wptr,
                            float* __restrict__ out) {
    __shared__ float s_rot[TB * 9];                // 9216 B
    __shared__ float s_pos[TB * 3];                // 3072 B
    __shared__ float s_cen[N_LINKS * N_SPH * 3];   // 768 B
    __shared__ float s_rad[N_LINKS * N_SPH];       // 256 B
    __shared__ float s_w;

    const int tid = threadIdx.x;
    const int gbase = blockIdx.x * TB;

    // ---- coalesced float4 staging of this block's rot/pos slabs ----
    {
        const float4* rot4 = (const float4*)(rot + (size_t)gbase * 9); // 16B aligned
        float4* sr4 = (float4*)s_rot;
        #pragma unroll
        for (int i = tid; i < TB * 9 / 4; i += TB) sr4[i] = rot4[i];   // 576 vec4

        const float4* pos4 = (const float4*)(pos + (size_t)gbase * 3); // 16B aligned
        float4* sp4 = (float4*)s_pos;
        if (tid < TB * 3 / 4) sp4[tid] = pos4[tid];                    // 192 vec4

        const float4* cen4 = (const float4*)cen;
        float4* sc4 = (float4*)s_cen;
        if (tid < N_LINKS * N_SPH * 3 / 4) sc4[tid] = cen4[tid];       // 48 vec4

        const float4* rad4 = (const float4*)rad;
        float4* sd4 = (float4*)s_rad;
        if (tid < N_LINKS * N_SPH / 4) sd4[tid] = rad4[tid];           // 16 vec4

        if (tid == 0) s_w = *wptr;
    }
    __syncthreads();

    const int l = tid & 7;   // link id (TB multiple of 8)

    // stride-9 / stride-3 shared reads: gcd(9,32)=gcd(3,32)=1 -> conflict-free
    const float r00 = s_rot[tid * 9 + 0], r01 = s_rot[tid * 9 + 1], r02 = s_rot[tid * 9 + 2];
    const float r10 = s_rot[tid * 9 + 3], r11 = s_rot[tid * 9 + 4], r12 = s_rot[tid * 9 + 5];
    const float r20 = s_rot[tid * 9 + 6], r21 = s_rot[tid * 9 + 7], r22 = s_rot[tid * 9 + 8];
    const float px = s_pos[tid * 3 + 0], py = s_pos[tid * 3 + 1], pz = s_pos[tid * 3 + 2];

    const float* lc = s_cen + l * (N_SPH * 3);
    const float* lr = s_rad + l * N_SPH;

    // ---- phase 1: compute all 8 gather offsets (no memory dependence) ----
    int off[N_SPH];
    float rr[N_SPH];
    #pragma unroll
    for (int s = 0; s < N_SPH; s++) {
        const float cx = lc[s * 3 + 0];
        const float cy = lc[s * 3 + 1];
        const float cz = lc[s * 3 + 2];
        const float x = fmaf(r00, cx, fmaf(r01, cy, fmaf(r02, cz, px)));
        const float y = fmaf(r10, cx, fmaf(r11, cy, fmaf(r12, cz, py)));
        const float z = fmaf(r20, cx, fmaf(r21, cy, fmaf(r22, cz, pz)));
        // IEEE division to match XLA's floor((p+1.28)/0.01) bit pattern
        int i0 = (int)floorf(__fdiv_rn(x + 1.28f, 0.01f));
        int i1 = (int)floorf(__fdiv_rn(y + 1.28f, 0.01f));
        int i2 = (int)floorf(__fdiv_rn(z + 1.28f, 0.01f));
        i0 = min(max(i0, 0), GRID_N - 1);
        i1 = min(max(i1, 0), GRID_N - 1);
        i2 = min(max(i2, 0), GRID_N - 1);
        off[s] = (i0 << 16) | (i1 << 8) | i2;
        rr[s] = lr[s];
    }

    // ---- phase 2: 8 independent gathers, batched for max MLP ----
    float m = -3.402823466e+38f;
    #pragma unroll
    for (int s = 0; s < N_SPH; s++) {
        m = fmaxf(m, rr[s] - __ldg(sdf + off[s]));
    }

    // clip(m - 0.01, 0, 0.5) / 0.25
    float res = fminf(fmaxf(m - 0.01f, 0.0f), 0.5f) * 4.0f;

    // sum over the 8 links (adjacent lanes within the warp)
    res += __shfl_xor_sync(0xffffffffu, res, 1);
    res += __shfl_xor_sync(0xffffffffu, res, 2);
    res += __shfl_xor_sync(0xffffffffu, res, 4);

    if (l == 0) out[(gbase + tid) >> 3] = s_w * res;
}

extern "C" void kernel_launch(void* const* d_in, const int* in_sizes, int n_in,
                              void* d_out, int out_size) {
    const float* pos = (const float*)d_in[0];
    const float* rot = (const float*)d_in[1];
    const float* cen = (const float*)d_in[2];
    const float* rad = (const float*)d_in[3];
    const float* sdf = (const float*)d_in[4];
    const float* w   = (const float*)d_in[5];
    float* out = (float*)d_out;

    voxel_collision_kernel<<<1024, TB>>>(pos, rot, cen, rad, sdf, w, out);
}

// round 3
// speedup vs baseline: 1.1210x; 1.1210x over previous
#include <cuda_runtime.h>

// Inputs (metadata order):
//  0: link_pos_seq   [1024,32,8,3]    f32
//  1: link_rot_seq   [1024,32,8,3,3]  f32
//  2: sphere_centers [8,8,3]          f32
//  3: sphere_radii   [8,8]            f32
//  4: sdf_grid       [256,256,256]    f32
//  5: weight         scalar           f32
// Output: [1024,32] f32

#define GRID_N 256
#define N_LINKS 8
#define N_SPH 8
#define TB 256

__global__ __launch_bounds__(TB, 8)
void voxel_collision_kernel(const float* __restrict__ pos,
                            const float* __restrict__ rot,
                            const float* __restrict__ cen,
                            const float* __restrict__ rad,
                            const float* __restrict__ sdf,
                            const float* __restrict__ wptr,
                            float* __restrict__ out) {
    __shared__ float s_rot[TB * 9];                // 9216 B
    __shared__ float s_pos[TB * 3];                // 3072 B
    __shared__ float s_cen[N_LINKS * N_SPH * 3];   // 768 B
    __shared__ float s_rad[N_LINKS * N_SPH];       // 256 B
    __shared__ float s_w;

    const int tid = threadIdx.x;
    const int gbase = blockIdx.x * TB;

    // ---- coalesced float4 staging of this block's rot/pos slabs ----
    {
        const float4* rot4 = (const float4*)(rot + (size_t)gbase * 9); // 16B aligned
        float4* sr4 = (float4*)s_rot;
        #pragma unroll
        for (int i = tid; i < TB * 9 / 4; i += TB) sr4[i] = rot4[i];   // 576 vec4

        const float4* pos4 = (const float4*)(pos + (size_t)gbase * 3); // 16B aligned
        float4* sp4 = (float4*)s_pos;
        if (tid < TB * 3 / 4) sp4[tid] = pos4[tid];                    // 192 vec4

        const float4* cen4 = (const float4*)cen;
        float4* sc4 = (float4*)s_cen;
        if (tid < N_LINKS * N_SPH * 3 / 4) sc4[tid] = cen4[tid];       // 48 vec4

        const float4* rad4 = (const float4*)rad;
        float4* sd4 = (float4*)s_rad;
        if (tid < N_LINKS * N_SPH / 4) sd4[tid] = rad4[tid];           // 16 vec4

        if (tid == 0) s_w = *wptr;
    }
    __syncthreads();

    const int l = tid & 7;   // link id (TB multiple of 8)

    // stride-9 / stride-3 shared reads: gcd(9,32)=gcd(3,32)=1 -> conflict-free
    const float r00 = s_rot[tid * 9 + 0], r01 = s_rot[tid * 9 + 1], r02 = s_rot[tid * 9 + 2];
    const float r10 = s_rot[tid * 9 + 3], r11 = s_rot[tid * 9 + 4], r12 = s_rot[tid * 9 + 5];
    const float r20 = s_rot[tid * 9 + 6], r21 = s_rot[tid * 9 + 7], r22 = s_rot[tid * 9 + 8];
    const float px = s_pos[tid * 3 + 0], py = s_pos[tid * 3 + 1], pz = s_pos[tid * 3 + 2];

    const float* lc = s_cen + l * (N_SPH * 3);
    const float* lr = s_rad + l * N_SPH;

    // Single interleaved loop: 8 mutually independent gathers (ptxas batches
    // the LDGs up front; serial dep only through the running max).
    float m = -3.402823466e+38f;
    #pragma unroll
    for (int s = 0; s < N_SPH; s++) {
        const float cx = lc[s * 3 + 0];
        const float cy = lc[s * 3 + 1];
        const float cz = lc[s * 3 + 2];
        const float x = fmaf(r00, cx, fmaf(r01, cy, fmaf(r02, cz, px)));
        const float y = fmaf(r10, cx, fmaf(r11, cy, fmaf(r12, cz, py)));
        const float z = fmaf(r20, cx, fmaf(r21, cy, fmaf(r22, cz, pz)));
        // IEEE division to match XLA's floor((p+1.28)/0.01) bit pattern
        int i0 = (int)floorf(__fdiv_rn(x + 1.28f, 0.01f));
        int i1 = (int)floorf(__fdiv_rn(y + 1.28f, 0.01f));
        int i2 = (int)floorf(__fdiv_rn(z + 1.28f, 0.01f));
        i0 = min(max(i0, 0), GRID_N - 1);
        i1 = min(max(i1, 0), GRID_N - 1);
        i2 = min(max(i2, 0), GRID_N - 1);
        const float v = __ldg(sdf + (((size_t)i0 << 16) | (i1 << 8) | i2));
        m = fmaxf(m, lr[s] - v);
    }

    // clip(m - 0.01, 0, 0.5) / 0.25
    float res = fminf(fmaxf(m - 0.01f, 0.0f), 0.5f) * 4.0f;

    // sum over the 8 links (adjacent lanes within the warp)
    res += __shfl_xor_sync(0xffffffffu, res, 1);
    res += __shfl_xor_sync(0xffffffffu, res, 2);
    res += __shfl_xor_sync(0xffffffffu, res, 4);

    if (l == 0) out[(gbase + tid) >> 3] = s_w * res;
}

extern "C" void kernel_launch(void* const* d_in, const int* in_sizes, int n_in,
                              void* d_out, int out_size) {
    const float* pos = (const float*)d_in[0];
    const float* rot = (const float*)d_in[1];
    const float* cen = (const float*)d_in[2];
    const float* rad = (const float*)d_in[3];
    const float* sdf = (const float*)d_in[4];
    const float* w   = (const float*)d_in[5];
    float* out = (float*)d_out;

    voxel_collision_kernel<<<1024, TB>>>(pos, rot, cen, rad, sdf, w, out);
}